// round 7
// baseline (speedup 1.0000x reference)
#include <cuda_runtime.h>
#include <cstdint>

#define NROWS 1000000
#define H     128
#define K     64
#define TEMP  30.0f
#define TILE_M 128
#define TTOT  ((NROWS + TILE_M - 1) / TILE_M)   // 7813
#define SSTR  132    // smem row stride in floats (132 % 32 == 4 -> conflict-free)
#define GRID3 148

// ---------------- scratch (no device mallocs allowed) ----------------
__device__ float    g_sums[K * H];
__device__ float    g_cnts[K];
__device__ uint32_t g_mu32[K * H];   // tf32-rounded mu bits

// ---------------- PTX helpers (baseline PTX only) ----------------
__device__ __forceinline__ uint32_t smem_u32(const void* p) {
    uint32_t a;
    asm("{ .reg .u64 t; cvta.to.shared.u64 t, %1; cvt.u32.u64 %0, t; }"
        : "=r"(a) : "l"(p));
    return a;
}
#define CP_ASYNC16(dst, src) \
    asm volatile("cp.async.cg.shared.global [%0], [%1], 16;" :: "r"(dst), "l"(src))
#define CP_COMMIT()  asm volatile("cp.async.commit_group;")
#define CP_WAIT1()   asm volatile("cp.async.wait_group 1;" ::: "memory")
#define CP_WAIT0()   asm volatile("cp.async.wait_group 0;" ::: "memory")

__device__ __forceinline__ uint32_t to_tf32(float f) {
    uint32_t u;
    asm("cvt.rna.tf32.f32 %0, %1;" : "=r"(u) : "f"(f));
    return u;
}
// m16n8k8 tf32 MMA, fp32 accum
__device__ __forceinline__ void mma_tf32(float* c, const uint32_t* a, const uint32_t* b) {
    asm volatile(
        "mma.sync.aligned.m16n8k8.row.col.f32.tf32.tf32.f32 "
        "{%0,%1,%2,%3}, {%4,%5,%6,%7}, {%8,%9}, {%0,%1,%2,%3};"
        : "+f"(c[0]), "+f"(c[1]), "+f"(c[2]), "+f"(c[3])
        : "r"(a[0]), "r"(a[1]), "r"(a[2]), "r"(a[3]), "r"(b[0]), "r"(b[1]));
}

// ---------------------------------------------------------------------------
__global__ void k_zero() {
    int i = blockIdx.x * blockDim.x + threadIdx.x;
    if (i < K * H) g_sums[i] = 0.0f;
    if (i < K)     g_cnts[i] = 0.0f;
}

// ---------------------------------------------------------------------------
// k1: row-wise L2 normalize z -> zn, accumulate per-community sums/counts.
// ---------------------------------------------------------------------------
__global__ void __launch_bounds__(256)
k_norm_acc(const float* __restrict__ z, const int* __restrict__ comm,
           float* __restrict__ zn) {
    __shared__ float s_sum[K * H];
    __shared__ float s_cnt[K];

    int tid = threadIdx.x;
    for (int i = tid; i < K * H; i += blockDim.x) s_sum[i] = 0.0f;
    if (tid < K) s_cnt[tid] = 0.0f;
    __syncthreads();

    int lane   = tid & 31;
    int warp   = tid >> 5;
    int nwarps = blockDim.x >> 5;

    for (long row = (long)blockIdx.x * nwarps + warp; row < NROWS;
         row += (long)gridDim.x * nwarps) {
        const float* zr = z + row * (long)H;
        float v0 = zr[lane];
        float v1 = zr[lane + 32];
        float v2 = zr[lane + 64];
        float v3 = zr[lane + 96];
        float ss = v0 * v0 + v1 * v1 + v2 * v2 + v3 * v3;
        #pragma unroll
        for (int o = 16; o; o >>= 1) ss += __shfl_xor_sync(0xffffffffu, ss, o);
        float inv = rsqrtf(ss);
        v0 *= inv; v1 *= inv; v2 *= inv; v3 *= inv;

        float* znr = zn + row * (long)H;
        znr[lane]      = v0;
        znr[lane + 32] = v1;
        znr[lane + 64] = v2;
        znr[lane + 96] = v3;

        int c = comm[row];
        float* sb = s_sum + c * H;
        atomicAdd(sb + lane,      v0);
        atomicAdd(sb + lane + 32, v1);
        atomicAdd(sb + lane + 64, v2);
        atomicAdd(sb + lane + 96, v3);
        if (lane == 0) atomicAdd(&s_cnt[c], 1.0f);
    }
    __syncthreads();

    for (int i = tid; i < K * H; i += blockDim.x)
        atomicAdd(&g_sums[i], s_sum[i]);
    if (tid < K) atomicAdd(&g_cnts[tid], s_cnt[tid]);
}

// ---------------------------------------------------------------------------
__global__ void k_mu(float* __restrict__ mu) {
    int i = blockIdx.x * blockDim.x + threadIdx.x;
    if (i < K * H) {
        float c = g_cnts[i / H];
        float v = g_sums[i] / fmaxf(c, 1.0f);
        mu[i] = v;
        g_mu32[i] = to_tf32(v);   // pre-rounded tf32 bits for the MMA B operand
    }
}

// ---------------------------------------------------------------------------
// k3: dist = zn @ mu^T via tf32 mma.sync.m16n8k8, fused softmax -> r.
//   Persistent 148 CTAs x 256 threads; tiles strided by GRID3. A tile is
//   double-buffered with cp.async groups (wait_group 1 keeps one prefetch in
//   flight). B (mu, tf32 bits) staged once per CTA. Warp owns one m16 tile
//   (16 rows) x 64 cols. k-permutation trick: logical k=q <-> physical col
//   8s+2q, k=q+4 <-> 8s+2q+1, so fragments are contiguous float2/uint2 LDS.
// ---------------------------------------------------------------------------
extern __shared__ float k3s[];

__global__ void __launch_bounds__(256, 1)
k_dist_mma(const float* __restrict__ zn,
           float* __restrict__ r, float* __restrict__ dist) {
    float*    As[2] = { k3s, k3s + TILE_M * SSTR };
    uint32_t* Bs    = (uint32_t*)(k3s + 2 * TILE_M * SSTR);

    int tid  = threadIdx.x;
    const int nt = (TTOT - (int)blockIdx.x + GRID3 - 1) / GRID3;

    uint32_t a_sb[2] = { smem_u32(As[0]), smem_u32(As[1]) };
    uint32_t b_sb    = smem_u32(Bs);

    // Group 0: B (once) + A(0)
    #pragma unroll
    for (int i = 0; i < 8; i++) {                       // B: 64 x 32 float4
        int idx = i * 256 + tid;
        int row = idx >> 5, ch = idx & 31;
        CP_ASYNC16(b_sb + (row * SSTR + ch * 4) * 4, g_mu32 + row * H + ch * 4);
    }
    {
        long base = (long)blockIdx.x * TILE_M;
        #pragma unroll
        for (int i = 0; i < 16; i++) {                  // A: 128 x 32 float4
            int idx = i * 256 + tid;
            int row = idx >> 5, ch = idx & 31;
            long gr = base + row; if (gr >= NROWS) gr = NROWS - 1;
            CP_ASYNC16(a_sb[0] + (row * SSTR + ch * 4) * 4, zn + gr * (long)H + ch * 4);
        }
    }
    CP_COMMIT();
    // Group 1: A(1)
    if (nt > 1) {
        long base = ((long)blockIdx.x + GRID3) * TILE_M;
        #pragma unroll
        for (int i = 0; i < 16; i++) {
            int idx = i * 256 + tid;
            int row = idx >> 5, ch = idx & 31;
            long gr = base + row; if (gr >= NROWS) gr = NROWS - 1;
            CP_ASYNC16(a_sb[1] + (row * SSTR + ch * 4) * 4, zn + gr * (long)H + ch * 4);
        }
    }
    CP_COMMIT();

    int lane = tid & 31, wid = tid >> 5;
    int qr = lane >> 2;        // quad row 0..7
    int qc = lane & 3;         // quad col 0..3

    const uint32_t* bBase = Bs + qr * SSTR + 2 * qc;

    for (int t = 0; t < nt; t++) {
        CP_WAIT1();            // A(t) complete (A(t+1) may still be in flight)
        __syncthreads();

        const float* aBase = As[t & 1] + (wid * 16 + qr) * SSTR + 2 * qc;

        float c[8][4];
        #pragma unroll
        for (int nt2 = 0; nt2 < 8; nt2++)
            #pragma unroll
            for (int q = 0; q < 4; q++) c[nt2][q] = 0.0f;

        #pragma unroll
        for (int s = 0; s < 16; s++) {
            int co = s * 8;
            float2 lo = *(const float2*)(aBase + co);
            float2 hi = *(const float2*)(aBase + 8 * SSTR + co);
            uint32_t ua[4] = { to_tf32(lo.x), to_tf32(hi.x),
                               to_tf32(lo.y), to_tf32(hi.y) };
            #pragma unroll
            for (int n = 0; n < 8; n++) {
                uint2 ub = *(const uint2*)(bBase + n * 8 * SSTR + co);
                mma_tf32(c[n], ua, (const uint32_t*)&ub);
            }
        }

        __syncthreads();       // everyone done reading As[t&1]

        // Prefetch A(t+2) into the buffer just freed.
        if (t + 2 < nt) {
            long base = ((long)blockIdx.x + (long)(t + 2) * GRID3) * TILE_M;
            uint32_t buf = a_sb[t & 1];
            #pragma unroll
            for (int i = 0; i < 16; i++) {
                int idx = i * 256 + tid;
                int row = idx >> 5, ch = idx & 31;
                long gr = base + row; if (gr >= NROWS) gr = NROWS - 1;
                CP_ASYNC16(buf + (row * SSTR + ch * 4) * 4, zn + gr * (long)H + ch * 4);
            }
        }
        CP_COMMIT();           // commit every iteration to keep group count in step

        // Epilogue (overlaps the prefetch): rows ra = qr, rb = qr+8 of warp tile.
        long base = ((long)blockIdx.x + (long)t * GRID3) * TILE_M;
        long ra = base + wid * 16 + qr;
        long rb = ra + 8;

        float va[16], vb[16];
        #pragma unroll
        for (int n = 0; n < 8; n++) {
            va[2 * n] = c[n][0]; va[2 * n + 1] = c[n][1];
            vb[2 * n] = c[n][2]; vb[2 * n + 1] = c[n][3];
        }

        float mxa = va[0], mxb = vb[0];
        #pragma unroll
        for (int i = 1; i < 16; i++) {
            mxa = fmaxf(mxa, va[i]);
            mxb = fmaxf(mxb, vb[i]);
        }
        mxa = fmaxf(mxa, __shfl_xor_sync(0xffffffffu, mxa, 1));
        mxa = fmaxf(mxa, __shfl_xor_sync(0xffffffffu, mxa, 2));
        mxb = fmaxf(mxb, __shfl_xor_sync(0xffffffffu, mxb, 1));
        mxb = fmaxf(mxb, __shfl_xor_sync(0xffffffffu, mxb, 2));

        float ea[16], eb[16], sa = 0.0f, sbv = 0.0f;
        #pragma unroll
        for (int i = 0; i < 16; i++) {
            ea[i] = __expf(TEMP * (va[i] - mxa)); sa  += ea[i];
            eb[i] = __expf(TEMP * (vb[i] - mxb)); sbv += eb[i];
        }
        sa  += __shfl_xor_sync(0xffffffffu, sa, 1);
        sa  += __shfl_xor_sync(0xffffffffu, sa, 2);
        sbv += __shfl_xor_sync(0xffffffffu, sbv, 1);
        sbv += __shfl_xor_sync(0xffffffffu, sbv, 2);
        float isa = 1.0f / sa, isb = 1.0f / sbv;

        int colb = qc * 2;
        if (ra < NROWS) {
            float* dr = dist + ra * (long)K + colb;
            float* rr = r    + ra * (long)K + colb;
            #pragma unroll
            for (int n = 0; n < 8; n++) {
                *(float2*)(dr + n * 8) = make_float2(va[2 * n], va[2 * n + 1]);
                *(float2*)(rr + n * 8) = make_float2(ea[2 * n] * isa, ea[2 * n + 1] * isa);
            }
        }
        if (rb < NROWS) {
            float* dr = dist + rb * (long)K + colb;
            float* rr = r    + rb * (long)K + colb;
            #pragma unroll
            for (int n = 0; n < 8; n++) {
                *(float2*)(dr + n * 8) = make_float2(vb[2 * n], vb[2 * n + 1]);
                *(float2*)(rr + n * 8) = make_float2(eb[2 * n] * isb, eb[2 * n + 1] * isb);
            }
        }
    }
}

// ---------------------------------------------------------------------------
// kernel_launch: out layout = zn [N*H] | mu [K*H] | r [N*K] | dist [N*K]
// ---------------------------------------------------------------------------
extern "C" void kernel_launch(void* const* d_in, const int* in_sizes, int n_in,
                              void* d_out, int out_size) {
    const float* z    = (const float*)d_in[0];
    const int*   comm = (const int*)d_in[1];

    float* out  = (float*)d_out;
    float* zn   = out;
    float* mu   = zn + (long)NROWS * H;
    float* rr   = mu + (long)K * H;
    float* dist = rr + (long)NROWS * K;

    const int k3_smem_bytes = (2 * TILE_M + K) * SSTR * sizeof(float);  // 168960
    static bool attr_set = false;
    if (!attr_set) {
        cudaFuncSetAttribute(k_dist_mma,
                             cudaFuncAttributeMaxDynamicSharedMemorySize,
                             k3_smem_bytes);
        attr_set = true;
    }

    k_zero<<<(K * H + 255) / 256, 256>>>();
    k_norm_acc<<<592, 256>>>(z, comm, zn);
    k_mu<<<(K * H + 255) / 256, 256>>>(mu);
    k_dist_mma<<<GRID3, 256, k3_smem_bytes>>>(zn, rr, dist);
}

// round 8
// speedup vs baseline: 1.1601x; 1.1601x over previous
#include <cuda_runtime.h>
#include <cstdint>

#define NROWS 1000000
#define H     128
#define K     64
#define TEMP  30.0f
#define TILE_M 128
#define TTOT  ((NROWS + TILE_M - 1) / TILE_M)   // 7813
#define SSTR  132    // smem row stride (132 % 32 == 4 -> conflict-free quads)

// ---------------- scratch (no device mallocs allowed) ----------------
__device__ float    g_sums[K * H];
__device__ float    g_cnts[K];
__device__ uint32_t g_mu32[K * H];   // tf32-rounded mu bits

// ---------------- PTX helpers (baseline PTX only) ----------------
__device__ __forceinline__ uint32_t to_tf32(float f) {
    uint32_t u;
    asm("cvt.rna.tf32.f32 %0, %1;" : "=r"(u) : "f"(f));
    return u;
}
// m16n8k8 tf32 MMA, fp32 accum
__device__ __forceinline__ void mma_tf32(float* c, const uint32_t* a, const uint32_t* b) {
    asm volatile(
        "mma.sync.aligned.m16n8k8.row.col.f32.tf32.tf32.f32 "
        "{%0,%1,%2,%3}, {%4,%5,%6,%7}, {%8,%9}, {%0,%1,%2,%3};"
        : "+f"(c[0]), "+f"(c[1]), "+f"(c[2]), "+f"(c[3])
        : "r"(a[0]), "r"(a[1]), "r"(a[2]), "r"(a[3]), "r"(b[0]), "r"(b[1]));
}

// ---------------------------------------------------------------------------
__global__ void k_zero() {
    int i = blockIdx.x * blockDim.x + threadIdx.x;
    if (i < K * H) g_sums[i] = 0.0f;
    if (i < K)     g_cnts[i] = 0.0f;
}

// ---------------------------------------------------------------------------
// k1: row-wise L2 normalize z -> zn, accumulate per-community sums/counts.
// ---------------------------------------------------------------------------
__global__ void __launch_bounds__(256)
k_norm_acc(const float* __restrict__ z, const int* __restrict__ comm,
           float* __restrict__ zn) {
    __shared__ float s_sum[K * H];
    __shared__ float s_cnt[K];

    int tid = threadIdx.x;
    for (int i = tid; i < K * H; i += blockDim.x) s_sum[i] = 0.0f;
    if (tid < K) s_cnt[tid] = 0.0f;
    __syncthreads();

    int lane   = tid & 31;
    int warp   = tid >> 5;
    int nwarps = blockDim.x >> 5;

    for (long row = (long)blockIdx.x * nwarps + warp; row < NROWS;
         row += (long)gridDim.x * nwarps) {
        const float* zr = z + row * (long)H;
        float v0 = zr[lane];
        float v1 = zr[lane + 32];
        float v2 = zr[lane + 64];
        float v3 = zr[lane + 96];
        float ss = v0 * v0 + v1 * v1 + v2 * v2 + v3 * v3;
        #pragma unroll
        for (int o = 16; o; o >>= 1) ss += __shfl_xor_sync(0xffffffffu, ss, o);
        float inv = rsqrtf(ss);
        v0 *= inv; v1 *= inv; v2 *= inv; v3 *= inv;

        float* znr = zn + row * (long)H;
        znr[lane]      = v0;
        znr[lane + 32] = v1;
        znr[lane + 64] = v2;
        znr[lane + 96] = v3;

        int c = comm[row];
        float* sb = s_sum + c * H;
        atomicAdd(sb + lane,      v0);
        atomicAdd(sb + lane + 32, v1);
        atomicAdd(sb + lane + 64, v2);
        atomicAdd(sb + lane + 96, v3);
        if (lane == 0) atomicAdd(&s_cnt[c], 1.0f);
    }
    __syncthreads();

    for (int i = tid; i < K * H; i += blockDim.x)
        atomicAdd(&g_sums[i], s_sum[i]);
    if (tid < K) atomicAdd(&g_cnts[tid], s_cnt[tid]);
}

// ---------------------------------------------------------------------------
__global__ void k_mu(float* __restrict__ mu) {
    int i = blockIdx.x * blockDim.x + threadIdx.x;
    if (i < K * H) {
        float c = g_cnts[i / H];
        float v = g_sums[i] / fmaxf(c, 1.0f);
        mu[i] = v;
        g_mu32[i] = to_tf32(v);   // pre-rounded tf32 bits for the MMA B operand
    }
}

// ---------------------------------------------------------------------------
// k3: dist = zn @ mu^T via tf32 mma.sync.m16n8k8, fused softmax -> r.
//   A is NOT staged: for fixed k-step s, a quad's A fragment covers exactly
//   one 32B sector of one zn row, touched exactly once kernel-wide (zero
//   reuse) -> direct LDG.64 is DRAM-optimal. Only B (mu tf32 bits) lives in
//   smem (static, 33 KB -> 3 CTAs/SM). One barrier total.
//   Warp owns 32 rows (2 x m16), all 64 cols. k-permutation: logical k=q <->
//   physical col 8s+2q, k=q+4 <-> 8s+2q+1 (dot product is k-perm invariant).
// ---------------------------------------------------------------------------
__global__ void __launch_bounds__(128, 3)
k_dist_mma(const float* __restrict__ zn,
           float* __restrict__ r, float* __restrict__ dist) {
    __shared__ uint32_t Bs[K * SSTR];

    int tid  = threadIdx.x;
    long base = (long)blockIdx.x * TILE_M;

    // Stage B: 64 rows x 32 uint4
    #pragma unroll
    for (int i = 0; i < 16; i++) {
        int idx = i * 128 + tid;
        int row = idx >> 5, ch = idx & 31;
        *(uint4*)&Bs[row * SSTR + ch * 4] = *(const uint4*)(g_mu32 + row * H + ch * 4);
    }
    __syncthreads();

    int lane = tid & 31, wid = tid >> 5;
    int qr = lane >> 2;        // quad row 0..7
    int qc = lane & 3;         // quad col 0..3

    // Row indices (clamped independently; duplicate rows in the tail tile are
    // computed redundantly but only rows < NROWS are stored).
    long rowA[2], rowB[2];
    const float* aLo[2];
    const float* aHi[2];
    #pragma unroll
    for (int mt = 0; mt < 2; mt++) {
        rowA[mt] = base + wid * 32 + mt * 16 + qr;
        rowB[mt] = rowA[mt] + 8;
        long ca = rowA[mt] < NROWS ? rowA[mt] : (NROWS - 1);
        long cb = rowB[mt] < NROWS ? rowB[mt] : (NROWS - 1);
        aLo[mt] = zn + ca * (long)H + 2 * qc;
        aHi[mt] = zn + cb * (long)H + 2 * qc;
    }

    const uint32_t* bBase = Bs + qr * SSTR + 2 * qc;

    float c[2][8][4];
    #pragma unroll
    for (int mt = 0; mt < 2; mt++)
        #pragma unroll
        for (int n = 0; n < 8; n++)
            #pragma unroll
            for (int q = 0; q < 4; q++) c[mt][n][q] = 0.0f;

    #pragma unroll
    for (int s = 0; s < 16; s++) {
        int co = s * 8;
        uint32_t ua[2][4];
        #pragma unroll
        for (int mt = 0; mt < 2; mt++) {
            float2 lo = *(const float2*)(aLo[mt] + co);
            float2 hi = *(const float2*)(aHi[mt] + co);
            ua[mt][0] = to_tf32(lo.x);
            ua[mt][1] = to_tf32(hi.x);
            ua[mt][2] = to_tf32(lo.y);
            ua[mt][3] = to_tf32(hi.y);
        }
        #pragma unroll
        for (int n = 0; n < 8; n++) {
            uint2 ub = *(const uint2*)(bBase + n * 8 * SSTR + co);
            mma_tf32(c[0][n], ua[0], (const uint32_t*)&ub);
            mma_tf32(c[1][n], ua[1], (const uint32_t*)&ub);
        }
    }

    // Epilogue: quad-shuffle softmax, float2 stores.
    #pragma unroll
    for (int mt = 0; mt < 2; mt++) {
        float va[16], vb[16];
        #pragma unroll
        for (int n = 0; n < 8; n++) {
            va[2 * n] = c[mt][n][0]; va[2 * n + 1] = c[mt][n][1];
            vb[2 * n] = c[mt][n][2]; vb[2 * n + 1] = c[mt][n][3];
        }

        float mxa = va[0], mxb = vb[0];
        #pragma unroll
        for (int i = 1; i < 16; i++) {
            mxa = fmaxf(mxa, va[i]);
            mxb = fmaxf(mxb, vb[i]);
        }
        mxa = fmaxf(mxa, __shfl_xor_sync(0xffffffffu, mxa, 1));
        mxa = fmaxf(mxa, __shfl_xor_sync(0xffffffffu, mxa, 2));
        mxb = fmaxf(mxb, __shfl_xor_sync(0xffffffffu, mxb, 1));
        mxb = fmaxf(mxb, __shfl_xor_sync(0xffffffffu, mxb, 2));

        float ea[16], eb[16], sa = 0.0f, sbv = 0.0f;
        #pragma unroll
        for (int i = 0; i < 16; i++) {
            ea[i] = __expf(TEMP * (va[i] - mxa)); sa  += ea[i];
            eb[i] = __expf(TEMP * (vb[i] - mxb)); sbv += eb[i];
        }
        sa  += __shfl_xor_sync(0xffffffffu, sa, 1);
        sa  += __shfl_xor_sync(0xffffffffu, sa, 2);
        sbv += __shfl_xor_sync(0xffffffffu, sbv, 1);
        sbv += __shfl_xor_sync(0xffffffffu, sbv, 2);
        float isa = 1.0f / sa, isb = 1.0f / sbv;

        int colb = qc * 2;
        if (rowA[mt] < NROWS) {
            float* dr = dist + rowA[mt] * (long)K + colb;
            float* rr = r    + rowA[mt] * (long)K + colb;
            #pragma unroll
            for (int n = 0; n < 8; n++) {
                *(float2*)(dr + n * 8) = make_float2(va[2 * n], va[2 * n + 1]);
                *(float2*)(rr + n * 8) = make_float2(ea[2 * n] * isa, ea[2 * n + 1] * isa);
            }
        }
        if (rowB[mt] < NROWS) {
            float* dr = dist + rowB[mt] * (long)K + colb;
            float* rr = r    + rowB[mt] * (long)K + colb;
            #pragma unroll
            for (int n = 0; n < 8; n++) {
                *(float2*)(dr + n * 8) = make_float2(vb[2 * n], vb[2 * n + 1]);
                *(float2*)(rr + n * 8) = make_float2(eb[2 * n] * isb, eb[2 * n + 1] * isb);
            }
        }
    }
}

// ---------------------------------------------------------------------------
// kernel_launch: out layout = zn [N*H] | mu [K*H] | r [N*K] | dist [N*K]
// ---------------------------------------------------------------------------
extern "C" void kernel_launch(void* const* d_in, const int* in_sizes, int n_in,
                              void* d_out, int out_size) {
    const float* z    = (const float*)d_in[0];
    const int*   comm = (const int*)d_in[1];

    float* out  = (float*)d_out;
    float* zn   = out;
    float* mu   = zn + (long)NROWS * H;
    float* rr   = mu + (long)K * H;
    float* dist = rr + (long)NROWS * K;

    k_zero<<<(K * H + 255) / 256, 256>>>();
    k_norm_acc<<<592, 256>>>(z, comm, zn);
    k_mu<<<(K * H + 255) / 256, 256>>>(mu);
    k_dist_mma<<<TTOT, 128>>>(zn, rr, dist);
}

// round 9
// speedup vs baseline: 1.2146x; 1.0469x over previous
#include <cuda_runtime.h>
#include <cstdint>

#define NROWS 1000000
#define H     128
#define K     64
#define TEMP  30.0f
#define TILE_M 128
#define TTOT  ((NROWS + TILE_M - 1) / TILE_M)   // 7813
#define BSTR  144    // B smem row stride in floats: 36 x 16B, 36 % 8 == 4
                     // -> LDS.128 phase groups (4qr+qc+4u) mod 8 distinct per octet

// ---------------- scratch (no device mallocs allowed) ----------------
__device__ float    g_sums[K * H];
__device__ float    g_cnts[K];
__device__ uint32_t g_mu32[K * H];   // tf32-rounded mu bits

// ---------------- PTX helpers (baseline PTX only) ----------------
__device__ __forceinline__ uint32_t to_tf32(float f) {
    uint32_t u;
    asm("cvt.rna.tf32.f32 %0, %1;" : "=r"(u) : "f"(f));
    return u;
}
// m16n8k8 tf32 MMA, fp32 accum
__device__ __forceinline__ void mma_tf32(float* c, const uint32_t* a, const uint32_t* b) {
    asm volatile(
        "mma.sync.aligned.m16n8k8.row.col.f32.tf32.tf32.f32 "
        "{%0,%1,%2,%3}, {%4,%5,%6,%7}, {%8,%9}, {%0,%1,%2,%3};"
        : "+f"(c[0]), "+f"(c[1]), "+f"(c[2]), "+f"(c[3])
        : "r"(a[0]), "r"(a[1]), "r"(a[2]), "r"(a[3]), "r"(b[0]), "r"(b[1]));
}

// ---------------------------------------------------------------------------
__global__ void k_zero() {
    int i = blockIdx.x * blockDim.x + threadIdx.x;
    if (i < K * H) g_sums[i] = 0.0f;
    if (i < K)     g_cnts[i] = 0.0f;
}

// ---------------------------------------------------------------------------
// k1: row-wise L2 normalize z -> zn, accumulate per-community sums/counts.
// ---------------------------------------------------------------------------
__global__ void __launch_bounds__(256)
k_norm_acc(const float* __restrict__ z, const int* __restrict__ comm,
           float* __restrict__ zn) {
    __shared__ float s_sum[K * H];
    __shared__ float s_cnt[K];

    int tid = threadIdx.x;
    for (int i = tid; i < K * H; i += blockDim.x) s_sum[i] = 0.0f;
    if (tid < K) s_cnt[tid] = 0.0f;
    __syncthreads();

    int lane   = tid & 31;
    int warp   = tid >> 5;
    int nwarps = blockDim.x >> 5;

    for (long row = (long)blockIdx.x * nwarps + warp; row < NROWS;
         row += (long)gridDim.x * nwarps) {
        const float* zr = z + row * (long)H;
        float v0 = zr[lane];
        float v1 = zr[lane + 32];
        float v2 = zr[lane + 64];
        float v3 = zr[lane + 96];
        float ss = v0 * v0 + v1 * v1 + v2 * v2 + v3 * v3;
        #pragma unroll
        for (int o = 16; o; o >>= 1) ss += __shfl_xor_sync(0xffffffffu, ss, o);
        float inv = rsqrtf(ss);
        v0 *= inv; v1 *= inv; v2 *= inv; v3 *= inv;

        float* znr = zn + row * (long)H;
        znr[lane]      = v0;
        znr[lane + 32] = v1;
        znr[lane + 64] = v2;
        znr[lane + 96] = v3;

        int c = comm[row];
        float* sb = s_sum + c * H;
        atomicAdd(sb + lane,      v0);
        atomicAdd(sb + lane + 32, v1);
        atomicAdd(sb + lane + 64, v2);
        atomicAdd(sb + lane + 96, v3);
        if (lane == 0) atomicAdd(&s_cnt[c], 1.0f);
    }
    __syncthreads();

    for (int i = tid; i < K * H; i += blockDim.x)
        atomicAdd(&g_sums[i], s_sum[i]);
    if (tid < K) atomicAdd(&g_cnts[tid], s_cnt[tid]);
}

// ---------------------------------------------------------------------------
__global__ void k_mu(float* __restrict__ mu) {
    int i = blockIdx.x * blockDim.x + threadIdx.x;
    if (i < K * H) {
        float c = g_cnts[i / H];
        float v = g_sums[i] / fmaxf(c, 1.0f);
        mu[i] = v;
        g_mu32[i] = to_tf32(v);   // pre-rounded tf32 bits for the MMA B operand
    }
}

// ---------------------------------------------------------------------------
// k3: dist = zn @ mu^T via tf32 mma.sync.m16n8k8, fused softmax -> r.
//   Super-step k mapping: steps (2u, 2u+1) of lane qc use physical h-cols
//   [16u+4qc, 16u+4qc+3] (A and B agree; dot product is k-perm invariant).
//   => A fragments: one LDG.128 per (mt, half, u)  — 16 per thread-tile.
//   => B fragments: one LDS.128 per (n, u)         — 64 per thread-tile.
//   A is never staged (zero reuse per 32B sector). B smem stride 144 floats
//   makes LDS.128 conflict-free. 4 CTAs/SM.
// ---------------------------------------------------------------------------
__global__ void __launch_bounds__(128, 4)
k_dist_mma(const float* __restrict__ zn,
           float* __restrict__ r, float* __restrict__ dist) {
    __shared__ uint32_t Bs[K * BSTR];

    int tid  = threadIdx.x;
    long base = (long)blockIdx.x * TILE_M;

    // Stage B: 64 rows x 32 uint4 (layout copy, padded stride)
    #pragma unroll
    for (int i = 0; i < 16; i++) {
        int idx = i * 128 + tid;
        int row = idx >> 5, ch = idx & 31;
        *(uint4*)&Bs[row * BSTR + ch * 4] = *(const uint4*)(g_mu32 + row * H + ch * 4);
    }
    __syncthreads();

    int lane = tid & 31, wid = tid >> 5;
    int qr = lane >> 2;        // groupID
    int qc = lane & 3;         // thread-in-group

    // Row indices (clamped; tail-tile duplicates computed but not stored).
    long rowA[2], rowB[2];
    const float* aLo[2];
    const float* aHi[2];
    #pragma unroll
    for (int mt = 0; mt < 2; mt++) {
        rowA[mt] = base + wid * 32 + mt * 16 + qr;
        rowB[mt] = rowA[mt] + 8;
        long ca = rowA[mt] < NROWS ? rowA[mt] : (NROWS - 1);
        long cb = rowB[mt] < NROWS ? rowB[mt] : (NROWS - 1);
        aLo[mt] = zn + ca * (long)H + 4 * qc;
        aHi[mt] = zn + cb * (long)H + 4 * qc;
    }

    const uint32_t* bBase = Bs + qr * BSTR + 4 * qc;

    float c[2][8][4];
    #pragma unroll
    for (int mt = 0; mt < 2; mt++)
        #pragma unroll
        for (int n = 0; n < 8; n++)
            #pragma unroll
            for (int q = 0; q < 4; q++) c[mt][n][q] = 0.0f;

    #pragma unroll
    for (int u = 0; u < 8; u++) {
        int co = u * 16;
        uint32_t ua0[2][4], ua1[2][4];
        #pragma unroll
        for (int mt = 0; mt < 2; mt++) {
            float4 lo = *(const float4*)(aLo[mt] + co);
            float4 hi = *(const float4*)(aHi[mt] + co);
            ua0[mt][0] = to_tf32(lo.x); ua0[mt][1] = to_tf32(hi.x);
            ua0[mt][2] = to_tf32(lo.y); ua0[mt][3] = to_tf32(hi.y);
            ua1[mt][0] = to_tf32(lo.z); ua1[mt][1] = to_tf32(hi.z);
            ua1[mt][2] = to_tf32(lo.w); ua1[mt][3] = to_tf32(hi.w);
        }
        #pragma unroll
        for (int n = 0; n < 8; n++) {
            uint4 b4 = *(const uint4*)(bBase + n * 8 * BSTR + co);
            uint32_t ub0[2] = { b4.x, b4.y };
            uint32_t ub1[2] = { b4.z, b4.w };
            mma_tf32(c[0][n], ua0[0], ub0);
            mma_tf32(c[1][n], ua0[1], ub0);
            mma_tf32(c[0][n], ua1[0], ub1);
            mma_tf32(c[1][n], ua1[1], ub1);
        }
    }

    // Epilogue: quad-shuffle softmax, float2 stores (D layout unchanged).
    #pragma unroll
    for (int mt = 0; mt < 2; mt++) {
        float va[16], vb[16];
        #pragma unroll
        for (int n = 0; n < 8; n++) {
            va[2 * n] = c[mt][n][0]; va[2 * n + 1] = c[mt][n][1];
            vb[2 * n] = c[mt][n][2]; vb[2 * n + 1] = c[mt][n][3];
        }

        float mxa = va[0], mxb = vb[0];
        #pragma unroll
        for (int i = 1; i < 16; i++) {
            mxa = fmaxf(mxa, va[i]);
            mxb = fmaxf(mxb, vb[i]);
        }
        mxa = fmaxf(mxa, __shfl_xor_sync(0xffffffffu, mxa, 1));
        mxa = fmaxf(mxa, __shfl_xor_sync(0xffffffffu, mxa, 2));
        mxb = fmaxf(mxb, __shfl_xor_sync(0xffffffffu, mxb, 1));
        mxb = fmaxf(mxb, __shfl_xor_sync(0xffffffffu, mxb, 2));

        float ea[16], eb[16], sa = 0.0f, sbv = 0.0f;
        #pragma unroll
        for (int i = 0; i < 16; i++) {
            ea[i] = __expf(TEMP * (va[i] - mxa)); sa  += ea[i];
            eb[i] = __expf(TEMP * (vb[i] - mxb)); sbv += eb[i];
        }
        sa  += __shfl_xor_sync(0xffffffffu, sa, 1);
        sa  += __shfl_xor_sync(0xffffffffu, sa, 2);
        sbv += __shfl_xor_sync(0xffffffffu, sbv, 1);
        sbv += __shfl_xor_sync(0xffffffffu, sbv, 2);
        float isa = 1.0f / sa, isb = 1.0f / sbv;

        int colb = qc * 2;
        if (rowA[mt] < NROWS) {
            float* dr = dist + rowA[mt] * (long)K + colb;
            float* rr = r    + rowA[mt] * (long)K + colb;
            #pragma unroll
            for (int n = 0; n < 8; n++) {
                *(float2*)(dr + n * 8) = make_float2(va[2 * n], va[2 * n + 1]);
                *(float2*)(rr + n * 8) = make_float2(ea[2 * n] * isa, ea[2 * n + 1] * isa);
            }
        }
        if (rowB[mt] < NROWS) {
            float* dr = dist + rowB[mt] * (long)K + colb;
            float* rr = r    + rowB[mt] * (long)K + colb;
            #pragma unroll
            for (int n = 0; n < 8; n++) {
                *(float2*)(dr + n * 8) = make_float2(vb[2 * n], vb[2 * n + 1]);
                *(float2*)(rr + n * 8) = make_float2(eb[2 * n] * isb, eb[2 * n + 1] * isb);
            }
        }
    }
}

// ---------------------------------------------------------------------------
// kernel_launch: out layout = zn [N*H] | mu [K*H] | r [N*K] | dist [N*K]
// ---------------------------------------------------------------------------
extern "C" void kernel_launch(void* const* d_in, const int* in_sizes, int n_in,
                              void* d_out, int out_size) {
    const float* z    = (const float*)d_in[0];
    const int*   comm = (const int*)d_in[1];

    float* out  = (float*)d_out;
    float* zn   = out;
    float* mu   = zn + (long)NROWS * H;
    float* rr   = mu + (long)K * H;
    float* dist = rr + (long)NROWS * K;

    k_zero<<<(K * H + 255) / 256, 256>>>();
    k_norm_acc<<<592, 256>>>(z, comm, zn);
    k_mu<<<(K * H + 255) / 256, 256>>>(mu);
    k_dist_mma<<<TTOT, 128>>>(zn, rr, dist);
}